// round 12
// baseline (speedup 1.0000x reference)
#include <cuda_runtime.h>

typedef unsigned long long ull;

#define B 8192
#define L 10
#define D 128
#define H 64
#define G4 256          // 4*H
#define OUT 5
#define TILE 64
#define NTHR 1024
#define QSTR 68
#define CSTR 68

// ------------------- global scratch -------------------
__device__ float g_xenc[(size_t)B * L * H];   // encoder hidden sequence
__device__ float g_pre[(size_t)B * L * H];    // x_enc @ W1x^T
__device__ float g_Wenc[192 * G4];            // [k][j*4+g]  k: 0..127 Wih, 128..191 Whh
__device__ float g_Wdec[69 * G4];             // [k][j*4+g]  k: 0..4 Wih, 5..68 Whh
__device__ float g_Wq[128 * H];               // [k][hh]     k: 0..63 W1h, 64..127 W1c

// ------------------- helpers -------------------
__device__ __forceinline__ ull pack2(float x, float y) {
    ull r; asm("mov.b64 %0, {%1, %2};" : "=l"(r) : "f"(x), "f"(y)); return r;
}
__device__ __forceinline__ ull dup2(float x) { return pack2(x, x); }
__device__ __forceinline__ float2 unpack2(ull v) {
    float2 f; asm("mov.b64 {%0, %1}, %2;" : "=f"(f.x), "=f"(f.y) : "l"(v)); return f;
}
__device__ __forceinline__ ull fma2(ull a, ull b, ull c) {
    ull d; asm("fma.rn.f32x2 %0, %1, %2, %3;" : "=l"(d) : "l"(a), "l"(b), "l"(c)); return d;
}
__device__ __forceinline__ float sigf(float x) {
    return __fdividef(1.f, 1.f + __expf(-x));
}
__device__ __forceinline__ float tanh_acc(float x) {
    return 1.f - __fdividef(2.f, __expf(2.f * x) + 1.f);
}
__device__ __forceinline__ float tanh_ap(float x) {
    float y; asm("tanh.approx.f32 %0, %1;" : "=f"(y) : "f"(x)); return y;
}

// =============================================================
// K0: repack weights
// =============================================================
__global__ void k_repack(const float* __restrict__ eWih, const float* __restrict__ eWhh,
                         const float* __restrict__ dWih, const float* __restrict__ dWhh,
                         const float* __restrict__ w1) {
    int idx = blockIdx.x * 256 + threadIdx.x;
    if (idx < 192 * G4) {
        int k = idx >> 8, c4 = idx & 255, j = c4 >> 2, g = c4 & 3;
        g_Wenc[idx] = (k < 128) ? eWih[(g * H + j) * D + k]
                                : eWhh[(g * H + j) * H + (k - 128)];
        return;
    }
    idx -= 192 * G4;
    if (idx < 69 * G4) {
        int k = idx >> 8, c4 = idx & 255, j = c4 >> 2, g = c4 & 3;
        g_Wdec[idx] = (k < 5) ? dWih[(g * H + j) * OUT + k]
                              : dWhh[(g * H + j) * H + (k - 5)];
        return;
    }
    idx -= 69 * G4;
    if (idx < 128 * H) {
        int k = idx >> 6, hh = idx & 63;
        g_Wq[idx] = (k < 64) ? w1[hh * 192 + k] : w1[hh * 192 + 64 + (k - 64)];
    }
}

// =============================================================
// K1: fused network, 1024 threads/CTA (32 warps), 64 rows/CTA.
// =============================================================
__global__ __launch_bounds__(NTHR, 1) void k_net(
    const float* __restrict__ x, const float* __restrict__ h0,
    const float* __restrict__ c0, const float* __restrict__ bih,
    const float* __restrict__ bhh, const float* __restrict__ enc_attn_w,
    const float* __restrict__ w1,
    const float* __restrict__ y_hist, const float* __restrict__ h0d,
    const float* __restrict__ c0d,
    const float* __restrict__ dec_attn_b1, const float* __restrict__ dec_attn_w2,
    const float* __restrict__ dec_bih, const float* __restrict__ dec_bhh,
    const float* __restrict__ fc_w, const float* __restrict__ fc_b,
    const float* __restrict__ fcout_w, const float* __restrict__ fcout_b,
    float* __restrict__ out) {
    extern __shared__ float sm[];

    const int tid = threadIdx.x;
    const int rt = tid & 31, jc = tid >> 5;      // 32 row-threads x 32 col-threads
    const int r0 = rt * 2, j0 = jc * 2, jc8 = jc * 8;
    const int b0 = blockIdx.x * TILE;
    const int rowp = tid >> 4, dg = tid & 15;    // 64 rows x 16 groups (staging / Phase B)

    // =========================================================
    // ENCODER PHASE
    // smem: As[192][64], Bs0/Bs1[32][256], Ws1x[64][64], ebias[256]
    // =========================================================
    {
        float* As    = sm;                    // 48 KB
        float* Bs0   = As + 192 * 64;         // 32 KB
        float* Bs1   = Bs0 + 32 * G4;         // 32 KB
        float* Ws1x  = Bs1 + 32 * G4;         // 16 KB
        float* ebias = Ws1x + 64 * 64;        // 1 KB

        // stage Ws1x[e][hh] = W1x[hh][e]
        for (int i = tid; i < 64 * 64; i += NTHR) {
            int e = i >> 6, hh = i & 63;
            Ws1x[e * 64 + hh] = w1[hh * 192 + 128 + e];
        }
        // fused encoder bias per gate-column
        if (tid < 256) {
            int j = tid >> 2, g = tid & 3;
            ebias[tid] = bih[g * H + j] + bhh[g * H + j];
        }

        // ---- attention weights in registers (exact; 8 d per thread) ----
        float4 at4[2];
        {
            float wx[L];
#pragma unroll
            for (int l = 0; l < L; l++) wx[l] = __ldg(enc_attn_w + 2 * H + l);
            at4[0] = make_float4(0.f, 0.f, 0.f, 0.f);
            at4[1] = make_float4(0.f, 0.f, 0.f, 0.f);
            const float* xp = x + (size_t)(b0 + rowp) * L * D + dg * 8;
#pragma unroll
            for (int l = 0; l < L; l++) {
#pragma unroll
                for (int i = 0; i < 2; i++) {
                    float4 v = *(const float4*)(xp + l * D + i * 4);
                    at4[i].x = fmaf(v.x, wx[l], at4[i].x);
                    at4[i].y = fmaf(v.y, wx[l], at4[i].y);
                    at4[i].z = fmaf(v.z, wx[l], at4[i].z);
                    at4[i].w = fmaf(v.w, wx[l], at4[i].w);
                }
            }
            float m = -1e30f;
#pragma unroll
            for (int i = 0; i < 2; i++)
                m = fmaxf(m, fmaxf(fmaxf(at4[i].x, at4[i].y), fmaxf(at4[i].z, at4[i].w)));
            m = fmaxf(m, __shfl_xor_sync(0xFFFFFFFFu, m, 1));
            m = fmaxf(m, __shfl_xor_sync(0xFFFFFFFFu, m, 2));
            m = fmaxf(m, __shfl_xor_sync(0xFFFFFFFFu, m, 4));
            m = fmaxf(m, __shfl_xor_sync(0xFFFFFFFFu, m, 8));
            float s = 0.f;
#pragma unroll
            for (int i = 0; i < 2; i++) {
                at4[i].x = __expf(at4[i].x - m); at4[i].y = __expf(at4[i].y - m);
                at4[i].z = __expf(at4[i].z - m); at4[i].w = __expf(at4[i].w - m);
                s += at4[i].x + at4[i].y + at4[i].z + at4[i].w;
            }
            s += __shfl_xor_sync(0xFFFFFFFFu, s, 1);
            s += __shfl_xor_sync(0xFFFFFFFFu, s, 2);
            s += __shfl_xor_sync(0xFFFFFFFFu, s, 4);
            s += __shfl_xor_sync(0xFFFFFFFFu, s, 8);
            float inv = __fdividef(1.f, s);
#pragma unroll
            for (int i = 0; i < 2; i++) {
                at4[i].x *= inv; at4[i].y *= inv; at4[i].z *= inv; at4[i].w *= inv;
            }
        }

        // ---- stage h0 transposed into As[128..191] (4 cols per thread) ----
        {
            const float* hp = h0 + (size_t)(b0 + rowp) * H + dg * 4;
            float4 v = *(const float4*)(hp);
            int j = 128 + dg * 4;
            As[(j + 0) * 64 + rowp] = v.x; As[(j + 1) * 64 + rowp] = v.y;
            As[(j + 2) * 64 + rowp] = v.z; As[(j + 3) * 64 + rowp] = v.w;
        }
        // ---- cell state (2 rows x 2 cols) ----
        float cr0[2], cr1[2];
#pragma unroll
        for (int i = 0; i < 2; i++) {
            cr0[i] = c0[(size_t)(b0 + r0 + i) * H + j0];
            cr1[i] = c0[(size_t)(b0 + r0 + i) * H + j0 + 1];
        }
        __syncthreads();

        for (int t = 0; t < L; t++) {
            // prefetch weight chunk 0 (32 k x 256)
            const float4* wp0 = (const float4*)g_Wenc + tid * 2;
            float4 f0 = wp0[0], f1 = wp0[1];

            // stage wi = at*x_t transposed into As[0..127] (8 d per thread)
            {
                const float* xp = x + ((size_t)(b0 + rowp) * L + t) * D + dg * 8;
#pragma unroll
                for (int i = 0; i < 2; i++) {
                    float4 xv = *(const float4*)(xp + i * 4);
                    int k = dg * 8 + i * 4;
                    As[(k + 0) * 64 + rowp] = xv.x * at4[i].x;
                    As[(k + 1) * 64 + rowp] = xv.y * at4[i].y;
                    As[(k + 2) * 64 + rowp] = xv.z * at4[i].z;
                    As[(k + 3) * 64 + rowp] = xv.w * at4[i].w;
                }
            }
            {
                float4* b4 = (float4*)Bs0 + tid * 2;
                b4[0] = f0; b4[1] = f1;
            }
            __syncthreads();

            // ---- gate GEMM: 2 rows x 8 cols per thread, 6 chunks ----
            ull acc[2][4];
            {
                ulonglong2 bv0 = *(const ulonglong2*)(ebias + jc8);
                ulonglong2 bv1 = *(const ulonglong2*)(ebias + jc8 + 4);
                acc[0][0] = bv0.x; acc[0][1] = bv0.y; acc[0][2] = bv1.x; acc[0][3] = bv1.y;
                acc[1][0] = bv0.x; acc[1][1] = bv0.y; acc[1][2] = bv1.x; acc[1][3] = bv1.y;
            }

            for (int kb = 0; kb < 6; kb++) {
                const float* Bsc = (kb & 1) ? Bs1 : Bs0;
                float4 n0, n1;
                if (kb < 5) {
                    const float4* wp = (const float4*)(g_Wenc + (kb + 1) * 32 * G4) + tid * 2;
                    n0 = wp[0]; n1 = wp[1];
                }
#pragma unroll
                for (int kk = 0; kk < 32; kk++) {
                    const float* ap = As + (kb * 32 + kk) * 64;
                    float2 a = *(const float2*)(ap + r0);
                    const ulonglong2* vp = (const ulonglong2*)(Bsc + kk * G4 + jc8);
                    ulonglong2 vA = vp[0], vB = vp[1];
                    ull ad0 = dup2(a.x), ad1 = dup2(a.y);
                    acc[0][0] = fma2(ad0, vA.x, acc[0][0]);
                    acc[0][1] = fma2(ad0, vA.y, acc[0][1]);
                    acc[0][2] = fma2(ad0, vB.x, acc[0][2]);
                    acc[0][3] = fma2(ad0, vB.y, acc[0][3]);
                    acc[1][0] = fma2(ad1, vA.x, acc[1][0]);
                    acc[1][1] = fma2(ad1, vA.y, acc[1][1]);
                    acc[1][2] = fma2(ad1, vB.x, acc[1][2]);
                    acc[1][3] = fma2(ad1, vB.y, acc[1][3]);
                }
                if (kb < 5) {
                    float* Bn = (kb & 1) ? Bs0 : Bs1;
                    float4* b4 = (float4*)Bn + tid * 2;
                    b4[0] = n0; b4[1] = n1;
                    __syncthreads();
                }
            }
            __syncthreads();   // all GEMM reads done

            // ---- activations (2 rows x 2 cols) ----
#pragma unroll
            for (int i = 0; i < 2; i++) {
                float2 u0 = unpack2(acc[i][0]), u1 = unpack2(acc[i][1]);
                float2 u2 = unpack2(acc[i][2]), u3 = unpack2(acc[i][3]);
                float cn0 = sigf(u0.y) * cr0[i] + sigf(u0.x) * tanh_acc(u1.x);
                float hn0 = sigf(u1.y) * tanh_acc(cn0);
                float cn1 = sigf(u2.y) * cr1[i] + sigf(u2.x) * tanh_acc(u3.x);
                float hn1 = sigf(u3.y) * tanh_acc(cn1);
                cr0[i] = cn0; cr1[i] = cn1;
                As[(128 + j0) * 64 + r0 + i]     = hn0;
                As[(128 + j0 + 1) * 64 + r0 + i] = hn1;
                *(float2*)(g_xenc + ((size_t)(b0 + r0 + i) * L + t) * H + j0) =
                    make_float2(hn0, hn1);
            }
            __syncthreads();   // h visible

            // ---- fused pre-GEMM: pre = h @ W1x^T (2 rows packed x 2 cols) ----
            {
                ull pc0 = 0, pc1 = 0;
#pragma unroll 8
                for (int e = 0; e < 64; e++) {
                    ull hA = *(const ull*)(As + (128 + e) * 64 + r0);
                    float2 w = *(const float2*)(Ws1x + e * 64 + j0);
                    pc0 = fma2(hA, dup2(w.x), pc0);
                    pc1 = fma2(hA, dup2(w.y), pc1);
                }
                float2 u0 = unpack2(pc0), u1 = unpack2(pc1);
                float* pb = g_pre + ((size_t)(b0 + r0) * L + t) * H + j0;
                const size_t rs = (size_t)L * H;
                *(float2*)(pb)      = make_float2(u0.x, u1.x);
                *(float2*)(pb + rs) = make_float2(u0.y, u1.y);
            }
            // next staging writes As[0..127], pre reads As[128..191] — disjoint
        }
    }
    __syncthreads();   // encoder smem dead; repartition for decoder

    // =========================================================
    // DECODER PHASE
    // =========================================================
    {
        float* Wdec  = sm;                    // [69][256]
        float* Wq    = Wdec + 69 * G4;        // [128][64]
        float* Acs   = Wq + 128 * H;          // [128][64]: 0..63 h, 64..127 c
        float* As2   = Acs + 128 * 64;        // [5][64]
        float* q_s   = As2 + 5 * 64;          // [64][QSTR]
        float* ctx_s = q_s + 64 * QSTR;       // [64][CSTR]
        float* w2_s  = ctx_s + 64 * CSTR;     // [64]
        float* b1_s  = w2_s + 64;             // [64]
        float* fcw_s = b1_s + 64;             // [5][72]
        float* fcb_s = fcw_s + 5 * 72;        // [8]
        float* fow_s = fcb_s + 8;             // [5][128]
        float* fob_s = fow_s + 5 * 128;       // [8]
        float* dbias = fob_s + 8;             // [256]

        const int rowq = tid >> 4, q16 = tid & 15;

        for (int i = tid; i < 69 * G4; i += NTHR)  Wdec[i] = g_Wdec[i];
        for (int i = tid; i < 128 * H; i += NTHR)  Wq[i]   = g_Wq[i];
        if (tid < 64) { w2_s[tid] = dec_attn_w2[tid]; b1_s[tid] = dec_attn_b1[tid]; }
        if (tid >= 64 && tid < 64 + 5 * 69) {
            int i = tid - 64;
            int o = i / 69, k = i % 69;
            fcw_s[o * 72 + k] = fc_w[i];
        }
        // FIX (R10 bug): 640 elements need tid range [384, 1024), not [512, 1152)
        if (tid >= 384) fow_s[tid - 384] = fcout_w[tid - 384];
        if (tid < 5) { fcb_s[tid] = fc_b[tid]; fob_s[tid] = fcout_b[tid]; }
        if (tid >= 64 + 5 * 69 && tid < 64 + 5 * 69 + 256) {   // [409, 665)
            int c4 = tid - (64 + 5 * 69);
            int j = c4 >> 2, g = c4 & 3;
            dbias[c4] = dec_bih[g * H + j] + dec_bhh[g * H + j];
        }

        {   // h0/c0 transposed (4 cols per thread)
            const float* hp = h0d + (size_t)(b0 + rowp) * H + dg * 4;
            const float* cp = c0d + (size_t)(b0 + rowp) * H + dg * 4;
            float4 hv = *(const float4*)(hp);
            float4 cv = *(const float4*)(cp);
            int j = dg * 4;
            Acs[(j + 0) * 64 + rowp] = hv.x; Acs[(j + 1) * 64 + rowp] = hv.y;
            Acs[(j + 2) * 64 + rowp] = hv.z; Acs[(j + 3) * 64 + rowp] = hv.w;
            Acs[(64 + j + 0) * 64 + rowp] = cv.x; Acs[(64 + j + 1) * 64 + rowp] = cv.y;
            Acs[(64 + j + 2) * 64 + rowp] = cv.z; Acs[(64 + j + 3) * 64 + rowp] = cv.w;
        }
        __syncthreads();

        for (int t = 0; t < L; t++) {
            // ---- Phase A: q = [h|c] @ Wq + b1 (2 rows packed x 2 cols) ----
            {
                ull qa0 = 0, qa1 = 0;
#pragma unroll 4
                for (int k = 0; k < 128; k++) {
                    ull hA = *(const ull*)(Acs + k * 64 + r0);
                    float2 w = *(const float2*)(Wq + k * H + j0);
                    qa0 = fma2(hA, dup2(w.x), qa0);
                    qa1 = fma2(hA, dup2(w.y), qa1);
                }
                float b1a = b1_s[j0], b1b = b1_s[j0 + 1];
                float2 u0 = unpack2(qa0), u1 = unpack2(qa1);
                q_s[(r0 + 0) * QSTR + j0]     = u0.x + b1a;
                q_s[(r0 + 1) * QSTR + j0]     = u0.y + b1a;
                q_s[(r0 + 0) * QSTR + j0 + 1] = u1.x + b1b;
                q_s[(r0 + 1) * QSTR + j0 + 1] = u1.y + b1b;
            }
            __syncthreads();

            // ---- Phase B: scores -> softmax -> ctx (16 lanes per row) ----
            {
                float4 qv = *(const float4*)(q_s + rowq * QSTR + q16 * 4);
                float4 w2v = *(const float4*)(w2_s + q16 * 4);
                const float* prep = g_pre + (size_t)(b0 + rowq) * L * H + q16 * 4;
                float at[L];
#pragma unroll
                for (int l = 0; l < L; l++) {
                    float4 p0 = *(const float4*)(prep + l * H);
                    float s;
                    s = tanh_ap(p0.x + qv.x) * w2v.x;
                    s = fmaf(tanh_ap(p0.y + qv.y), w2v.y, s);
                    s = fmaf(tanh_ap(p0.z + qv.z), w2v.z, s);
                    s = fmaf(tanh_ap(p0.w + qv.w), w2v.w, s);
                    s += __shfl_xor_sync(0xFFFFFFFFu, s, 1);
                    s += __shfl_xor_sync(0xFFFFFFFFu, s, 2);
                    s += __shfl_xor_sync(0xFFFFFFFFu, s, 4);
                    s += __shfl_xor_sync(0xFFFFFFFFu, s, 8);
                    at[l] = s;
                }
                float m = at[0];
#pragma unroll
                for (int l = 1; l < L; l++) m = fmaxf(m, at[l]);
                float ssum = 0.f;
#pragma unroll
                for (int l = 0; l < L; l++) { at[l] = __expf(at[l] - m); ssum += at[l]; }
                float inv = __fdividef(1.f, ssum);
#pragma unroll
                for (int l = 0; l < L; l++) at[l] *= inv;

                float4 cac = make_float4(0.f, 0.f, 0.f, 0.f);
                const float* xep = g_xenc + (size_t)(b0 + rowq) * L * H + q16 * 4;
#pragma unroll
                for (int l = 0; l < L; l++) {
                    float4 xv = *(const float4*)(xep + l * H);
                    cac.x = fmaf(at[l], xv.x, cac.x);
                    cac.y = fmaf(at[l], xv.y, cac.y);
                    cac.z = fmaf(at[l], xv.z, cac.z);
                    cac.w = fmaf(at[l], xv.w, cac.w);
                }
                *(float4*)(ctx_s + rowq * CSTR + q16 * 4) = cac;
            }
            __syncthreads();

            // ---- Phase E: y_tilde = [ctx|y_t] @ fc_w^T + fc_b ----
            if (tid < 5 * 64) {
                int row = tid & 63, o = tid >> 6;
                float s = fcb_s[o];
                const float* fw = fcw_s + o * 72;
                const float* cx = ctx_s + row * CSTR;
#pragma unroll 8
                for (int k = 0; k < 64; k++) s = fmaf(fw[k], cx[k], s);
                const float* yh = y_hist + ((size_t)(b0 + row) * L + t) * OUT;
#pragma unroll
                for (int k = 0; k < OUT; k++) s = fmaf(fw[64 + k], yh[k], s);
                As2[o * 64 + row] = s;
            }
            __syncthreads();

            // ---- Phase F: gates (2 rows x 8 cols, k = 5 + 64) ----
            ull acc[2][4];
            {
                ulonglong2 bv0 = *(const ulonglong2*)(dbias + jc8);
                ulonglong2 bv1 = *(const ulonglong2*)(dbias + jc8 + 4);
                acc[0][0] = bv0.x; acc[0][1] = bv0.y; acc[0][2] = bv1.x; acc[0][3] = bv1.y;
                acc[1][0] = bv0.x; acc[1][1] = bv0.y; acc[1][2] = bv1.x; acc[1][3] = bv1.y;
            }
#pragma unroll
            for (int k = 0; k < 5; k++) {
                float2 a = *(const float2*)(As2 + k * 64 + r0);
                const ulonglong2* vp = (const ulonglong2*)(Wdec + k * G4 + jc8);
                ulonglong2 vA = vp[0], vB = vp[1];
                ull ad0 = dup2(a.x), ad1 = dup2(a.y);
                acc[0][0] = fma2(ad0, vA.x, acc[0][0]);
                acc[0][1] = fma2(ad0, vA.y, acc[0][1]);
                acc[0][2] = fma2(ad0, vB.x, acc[0][2]);
                acc[0][3] = fma2(ad0, vB.y, acc[0][3]);
                acc[1][0] = fma2(ad1, vA.x, acc[1][0]);
                acc[1][1] = fma2(ad1, vA.y, acc[1][1]);
                acc[1][2] = fma2(ad1, vB.x, acc[1][2]);
                acc[1][3] = fma2(ad1, vB.y, acc[1][3]);
            }
#pragma unroll 8
            for (int k = 0; k < 64; k++) {
                float2 a = *(const float2*)(Acs + k * 64 + r0);
                const ulonglong2* vp = (const ulonglong2*)(Wdec + (5 + k) * G4 + jc8);
                ulonglong2 vA = vp[0], vB = vp[1];
                ull ad0 = dup2(a.x), ad1 = dup2(a.y);
                acc[0][0] = fma2(ad0, vA.x, acc[0][0]);
                acc[0][1] = fma2(ad0, vA.y, acc[0][1]);
                acc[0][2] = fma2(ad0, vB.x, acc[0][2]);
                acc[0][3] = fma2(ad0, vB.y, acc[0][3]);
                acc[1][0] = fma2(ad1, vA.x, acc[1][0]);
                acc[1][1] = fma2(ad1, vA.y, acc[1][1]);
                acc[1][2] = fma2(ad1, vB.x, acc[1][2]);
                acc[1][3] = fma2(ad1, vB.y, acc[1][3]);
            }
            __syncthreads();   // old-h reads done

            // ---- Phase G: LSTM cell, update h/c (2 rows x 2 cols) ----
#pragma unroll
            for (int i = 0; i < 2; i++) {
                float2 u0 = unpack2(acc[i][0]), u1 = unpack2(acc[i][1]);
                float2 u2 = unpack2(acc[i][2]), u3 = unpack2(acc[i][3]);
                float co0 = Acs[(64 + j0) * 64 + r0 + i];
                float co1 = Acs[(64 + j0 + 1) * 64 + r0 + i];
                float cn0 = sigf(u0.y) * co0 + sigf(u0.x) * tanh_acc(u1.x);
                float hn0 = sigf(u1.y) * tanh_acc(cn0);
                float cn1 = sigf(u2.y) * co1 + sigf(u2.x) * tanh_acc(u3.x);
                float hn1 = sigf(u3.y) * tanh_acc(cn1);
                Acs[(j0) * 64 + r0 + i]          = hn0;
                Acs[(j0 + 1) * 64 + r0 + i]      = hn1;
                Acs[(64 + j0) * 64 + r0 + i]     = cn0;
                Acs[(64 + j0 + 1) * 64 + r0 + i] = cn1;
            }
            __syncthreads();
        }

        // ---- out = [h | ctx] @ fcout_w^T + fcout_b ----
        if (tid < 5 * 64) {
            int row = tid & 63, o = tid >> 6;
            float s = fob_s[o];
            const float* fw = fow_s + o * 128;
#pragma unroll 8
            for (int k = 0; k < 64; k++) s = fmaf(fw[k], Acs[k * 64 + row], s);
            const float* cx = ctx_s + row * CSTR;
#pragma unroll 8
            for (int k = 0; k < 64; k++) s = fmaf(fw[64 + k], cx[k], s);
            out[(size_t)(b0 + row) * OUT + o] = s;
        }
    }
}

// =============================================================
// launcher
// =============================================================
extern "C" void kernel_launch(void* const* d_in, const int* in_sizes, int n_in,
                              void* d_out, int out_size) {
    const float* x           = (const float*)d_in[0];
    const float* y_hist      = (const float*)d_in[1];
    const float* h0_enc      = (const float*)d_in[2];
    const float* c0_enc      = (const float*)d_in[3];
    const float* h0_dec      = (const float*)d_in[4];
    const float* c0_dec      = (const float*)d_in[5];
    const float* enc_attn_w  = (const float*)d_in[6];
    // d_in[7] enc_attn_b: softmax-shift-invariant, unused
    const float* enc_Wih     = (const float*)d_in[8];
    const float* enc_Whh     = (const float*)d_in[9];
    const float* enc_bih     = (const float*)d_in[10];
    const float* enc_bhh     = (const float*)d_in[11];
    const float* dec_attn_w1 = (const float*)d_in[12];
    const float* dec_attn_b1 = (const float*)d_in[13];
    const float* dec_attn_w2 = (const float*)d_in[14];
    // d_in[15] dec_attn_b2: softmax-shift-invariant, unused
    const float* dec_Wih     = (const float*)d_in[16];
    const float* dec_Whh     = (const float*)d_in[17];
    const float* dec_bih     = (const float*)d_in[18];
    const float* dec_bhh     = (const float*)d_in[19];
    const float* fc_w        = (const float*)d_in[20];
    const float* fc_b        = (const float*)d_in[21];
    const float* fcout_w     = (const float*)d_in[22];
    const float* fcout_b     = (const float*)d_in[23];
    float* out = (float*)d_out;

    const int enc_sm = (192 * 64 + 2 * 32 * G4 + 64 * 64 + 256) * 4;    // 132096 B
    const int dec_sm = (69 * G4 + 128 * H + 128 * 64 + 5 * 64 +
                        64 * QSTR + 64 * CSTR + 64 + 64 +
                        5 * 72 + 8 + 5 * 128 + 8 + 256) * 4;            // 177888 B
    const int net_smem = (enc_sm > dec_sm) ? enc_sm : dec_sm;
    cudaFuncSetAttribute(k_net, cudaFuncAttributeMaxDynamicSharedMemorySize, net_smem);

    const int repack_n = 192 * G4 + 69 * G4 + 128 * H;
    k_repack<<<(repack_n + 255) / 256, 256>>>(
        enc_Wih, enc_Whh, dec_Wih, dec_Whh, dec_attn_w1);
    k_net<<<B / TILE, NTHR, net_smem>>>(
        x, h0_enc, c0_enc, enc_bih, enc_bhh, enc_attn_w, dec_attn_w1,
        y_hist, h0_dec, c0_dec, dec_attn_b1, dec_attn_w2,
        dec_bih, dec_bhh, fc_w, fc_b, fcout_w, fcout_b, out);
}